// round 14
// baseline (speedup 1.0000x reference)
#include <cuda_runtime.h>
#include <cuda_bf16.h>
#include <cstdint>

// ---------------------------------------------------------------------------
// SymbolicFeatureExtractor: per-row (seq_len, unique_count) -> 3 feats -> MLP.
// MLP output depends only on (seq_len, uniq) in [0,128]^2 -> 129x129x32 LUT.
//
// R14: SINGLE fused kernel. The first LUT_BLOCKS blocks build the LUT slice
// before their feat rows and publish with release semantics into g_lut_done;
// every warp acquire-polls g_lut_done just before its LUT gather (its last
// action, ~3 us into block life, while the LUT completes in <1 us -> the
// poll is one L2 read in steady state). g_lut_done is reset each invocation
// by a 4-byte cudaMemsetAsync (graph-capturable, allocation-free).
//
// feat path = proven R11 optimum (2 rows/warp, 512-slot per-warp table,
// no clears, 39 regs): pack = v*256 + row*128 + pos; x = slot^pack;
// x<128 <=> value+row match (cohort resolved; x==0 member counts 1).
// One syncwarp after each round's writes; none between reads and next
// writes (benign-misread analysis); exact ballot tail loop.
// ---------------------------------------------------------------------------

#define MAX_LEN 128
#define LUT_DIM 129
#define LUT_PAIRS (LUT_DIM * LUT_DIM)          // 16641

__device__ float g_lut[LUT_PAIRS * 32];
__device__ int   g_lut_done;                   // reset via cudaMemsetAsync

#define WARPS_PER_BLOCK 8
#define ROWS_PER_WARP 2
#define HASH_SLOTS 512                         // 16 KB/block

#define LUT_PAIRS_PER_WARP 4
#define LUT_PAIRS_PER_BLOCK (WARPS_PER_BLOCK * LUT_PAIRS_PER_WARP)   // 32
#define LUT_BLOCKS ((LUT_PAIRS + LUT_PAIRS_PER_BLOCK - 1) / LUT_PAIRS_PER_BLOCK) // 521

__device__ __forceinline__ int ld_acquire(const int* p) {
    int v;
    asm volatile("ld.acquire.gpu.global.b32 %0, [%1];" : "=r"(v) : "l"(p));
    return v;
}

// Count uniques for one row's 4 tokens. row_tag is 0 or 128 (row bit).
__device__ __forceinline__ int count_uniques(int* tab, const int4& iv,
                                             const int4& mv, int lane,
                                             int row_tag) {
    int vals[4] = {iv.x, iv.y, iv.z, iv.w};
    bool pend[4] = {mv.x != 0, mv.y != 0, mv.z != 0, mv.w != 0};

    int base_pos = row_tag + lane * 4;
    int pack[4];
    #pragma unroll
    for (int t = 0; t < 4; t++)
        pack[t] = vals[t] * 256 + (base_pos + t);   // (v<<8)|(row<<7)|pos

    int cnt = 0;
    unsigned h[4];

    // round 0: direct-mapped
    #pragma unroll
    for (int t = 0; t < 4; t++) {
        h[t] = (unsigned)vals[t] & (HASH_SLOTS - 1);
        if (pend[t]) tab[h[t]] = pack[t];
    }
    __syncwarp();                      // writes before reads (required)
    #pragma unroll
    for (int t = 0; t < 4; t++) {
        if (pend[t]) {
            int x = tab[h[t]] ^ pack[t];
            if ((unsigned)x < 128u) { pend[t] = false; cnt += (x == 0); }
        }
    }
    // no syncwarp: benign-misread analysis (header)

    // round 1: multiplicative hash, survivors only
    #pragma unroll
    for (int t = 0; t < 4; t++) {
        if (pend[t]) {
            h[t] = ((unsigned)vals[t] * 2654435761u) >> 23;
            tab[h[t]] = pack[t];
        }
    }
    __syncwarp();                      // writes before reads (required)
    #pragma unroll
    for (int t = 0; t < 4; t++) {
        if (pend[t]) {
            int x = tab[h[t]] ^ pack[t];
            if ((unsigned)x < 128u) { pend[t] = false; cnt += (x == 0); }
        }
    }

    // tail: smem-free cohort broadcast (exact; ~0 iterations typical).
    while (true) {
        bool any = pend[0] | pend[1] | pend[2] | pend[3];
        unsigned m = __ballot_sync(0xffffffffu, any);
        if (!m) break;
        int leader = __ffs(m) - 1;
        int myv = pend[0] ? vals[0] : pend[1] ? vals[1]
                : pend[2] ? vals[2] : vals[3];
        int lv = __shfl_sync(0xffffffffu, myv, leader);
        cnt += (lane == leader);
        #pragma unroll
        for (int t = 0; t < 4; t++)
            pend[t] &= (vals[t] != lv);
    }
    return cnt;
}

__global__ __launch_bounds__(WARPS_PER_BLOCK * 32, 6)
void fused_kernel(const int* __restrict__ ids, const int* __restrict__ mask,
                  const float* __restrict__ W1, const float* __restrict__ b1,
                  const float* __restrict__ W2, const float* __restrict__ b2,
                  float* __restrict__ out, int B) {
    __shared__ int table[WARPS_PER_BLOCK][HASH_SLOTS];

    int w    = threadIdx.x >> 5;
    int lane = threadIdx.x & 31;

    // ---- LUT phase: first LUT_BLOCKS blocks build their slice first ----
    if (blockIdx.x < LUT_BLOCKS) {
        int base = (blockIdx.x * WARPS_PER_BLOCK + w) * LUT_PAIRS_PER_WARP;
        if (base < LUT_PAIRS) {
            float w10 = W1[0 * 32 + lane];
            float w11 = W1[1 * 32 + lane];
            float w12 = W1[2 * 32 + lane];
            float bb1 = b1[lane];
            float bb2 = b2[lane];
            float w2c[32];
            #pragma unroll
            for (int k = 0; k < 32; k++) w2c[k] = W2[k * 32 + lane];

            #pragma unroll
            for (int p = 0; p < LUT_PAIRS_PER_WARP; p++) {
                int idx = base + p;
                if (idx >= LUT_PAIRS) break;
                int s = idx / LUT_DIM;
                int u = idx % LUT_DIM;

                float f0 = (float)s * (1.0f / MAX_LEN);
                float f1 = (float)u * (1.0f / MAX_LEN);
                float f2 = (s > 0) ? ((float)u / (float)s) : 0.0f;

                float hh = bb1;
                hh = fmaf(f0, w10, hh);
                hh = fmaf(f1, w11, hh);
                hh = fmaf(f2, w12, hh);
                hh = fmaxf(hh, 0.0f);

                float o = bb2;
                #pragma unroll
                for (int k = 0; k < 32; k++) {
                    float hk = __shfl_sync(0xffffffffu, hh, k);
                    o = fmaf(hk, w2c[k], o);
                }
                g_lut[(size_t)idx * 32 + lane] = fmaxf(o, 0.0f);
            }
        }
        __syncthreads();
        if (threadIdx.x == 0) {
            __threadfence();                        // release LUT stores
            atomicAdd(&g_lut_done, 1);
        }
    }

    // ---- feat phase (R11 optimum) ----
    int row0 = (blockIdx.x * WARPS_PER_BLOCK + w) * ROWS_PER_WARP;
    if (row0 >= B) return;
    int row1 = row0 + 1;
    bool has1 = row1 < B;
    int* tab = table[w];

    // Front-batch all 4 input loads (streaming: keep LUT resident in L2).
    const int4* id0 = (const int4*)(ids  + (size_t)row0 * MAX_LEN);
    const int4* mk0 = (const int4*)(mask + (size_t)row0 * MAX_LEN);
    const int4* id1 = (const int4*)(ids  + (size_t)row1 * MAX_LEN);
    const int4* mk1 = (const int4*)(mask + (size_t)row1 * MAX_LEN);
    int4 iv0 = __ldcs(id0 + lane);
    int4 mv0 = __ldcs(mk0 + lane);
    int4 iv1, mv1;
    if (has1) { iv1 = __ldcs(id1 + lane); mv1 = __ldcs(mk1 + lane); }
    else      { iv1 = make_int4(0,0,0,0); mv1 = make_int4(0,0,0,0); }

    int seq0 = mv0.x + mv0.y + mv0.z + mv0.w;
    int seq1 = mv1.x + mv1.y + mv1.z + mv1.w;

    int cnt0 = count_uniques(tab, iv0, mv0, lane, 0);
    int cnt1 = count_uniques(tab, iv1, mv1, lane, 128);

    // LUT index is linear in per-lane partials: one REDUX per row.
    int idx0 = __reduce_add_sync(0xffffffffu, seq0 * LUT_DIM + cnt0);
    int idx1 = __reduce_add_sync(0xffffffffu, seq1 * LUT_DIM + cnt1);

    // Acquire-wait for LUT publication (steady state: single L2 read).
    if (lane == 0) {
        while (ld_acquire(&g_lut_done) < LUT_BLOCKS)
            __nanosleep(64);
    }
    __syncwarp();

    float v0 = g_lut[(size_t)idx0 * 32 + lane];
    float v1 = g_lut[(size_t)idx1 * 32 + lane];
    __stcs(&out[(size_t)row0 * 32 + lane], v0);
    if (has1) __stcs(&out[(size_t)row1 * 32 + lane], v1);
}

extern "C" void kernel_launch(void* const* d_in, const int* in_sizes, int n_in,
                              void* d_out, int out_size) {
    const int*   ids  = (const int*)d_in[0];
    const int*   mask = (const int*)d_in[1];
    const float* W1   = (const float*)d_in[2];
    const float* b1   = (const float*)d_in[3];
    const float* W2   = (const float*)d_in[4];
    const float* b2   = (const float*)d_in[5];
    float* out = (float*)d_out;

    int B = in_sizes[0] / MAX_LEN;

    // Reset the publication counter (graph-capturable, no allocation).
    void* done_ptr = nullptr;
    cudaGetSymbolAddress(&done_ptr, g_lut_done);
    cudaMemsetAsync(done_ptr, 0, sizeof(int));

    int rows_per_block = WARPS_PER_BLOCK * ROWS_PER_WARP;
    int blocks = (B + rows_per_block - 1) / rows_per_block;
    fused_kernel<<<blocks, WARPS_PER_BLOCK * 32>>>(ids, mask, W1, b1, W2, b2,
                                                   out, B);
}

// round 15
// speedup vs baseline: 1.5458x; 1.5458x over previous
#include <cuda_runtime.h>
#include <cuda_bf16.h>
#include <cstdint>

// ---------------------------------------------------------------------------
// SymbolicFeatureExtractor: per-row (seq_len, unique_count) -> 3 feats -> MLP.
// MLP output depends only on (seq_len, uniq) in [0,128]^2 -> 129x129x32 LUT
// (2.1 MB, L2-resident; inputs/outputs use streaming hints to protect it).
//
// R15 = R11 champion (two rows per warp, 512-slot per-warp table, no clears)
// squeezed to <=32 registers so the SM runs 8 blocks (64 warps, occ ~83%)
// instead of 6: hash values are rematerialized at the read site (round 0:
// one AND; round 1: IMAD+SHR, survivors only) instead of kept live, and the
// always-true row1 bound (B % 16 == 0) is dropped.
//
// Unique counting (proven R8/R11): pack = v*256 + row*128 + pos;
// x = slot^pack; x<128 <=> value AND row match (cohort resolved; the x==0
// member is the unique winner, counts 1). One syncwarp after each round's
// writes; none between reads and next writes (benign-misread: a misdirected
// resolve never has x==0; cohort still counted exactly once by the round-1
// winner or the exact tail loop). Row isolation via the tail loop's
// unconditional ballot (warp-convergent, data-dependent on completed reads)
// + row bit as defense-in-depth. No clears ever: every read is preceded by
// that token's own same-round write to the same slot.
// ---------------------------------------------------------------------------

#define MAX_LEN 128
#define LUT_DIM 129

__device__ float g_lut[LUT_DIM * LUT_DIM * 32];

#define LUT_PAIRS_PER_WARP 8

__global__ __launch_bounds__(256)
void build_lut_kernel(const float* __restrict__ W1, const float* __restrict__ b1,
                      const float* __restrict__ W2, const float* __restrict__ b2) {
    int warp_in_block = threadIdx.x >> 5;
    int lane = threadIdx.x & 31;
    int base = (blockIdx.x * (blockDim.x >> 5) + warp_in_block) * LUT_PAIRS_PER_WARP;
    if (base >= LUT_DIM * LUT_DIM) return;

    float w10 = W1[0 * 32 + lane];
    float w11 = W1[1 * 32 + lane];
    float w12 = W1[2 * 32 + lane];
    float bb1 = b1[lane];
    float bb2 = b2[lane];
    float w2c[32];
    #pragma unroll
    for (int k = 0; k < 32; k++) w2c[k] = W2[k * 32 + lane];

    #pragma unroll
    for (int p = 0; p < LUT_PAIRS_PER_WARP; p++) {
        int idx = base + p;
        if (idx >= LUT_DIM * LUT_DIM) break;
        int s = idx / LUT_DIM;
        int u = idx % LUT_DIM;

        float f0 = (float)s * (1.0f / MAX_LEN);
        float f1 = (float)u * (1.0f / MAX_LEN);
        float f2 = (s > 0) ? ((float)u / (float)s) : 0.0f;

        float h = bb1;
        h = fmaf(f0, w10, h);
        h = fmaf(f1, w11, h);
        h = fmaf(f2, w12, h);
        h = fmaxf(h, 0.0f);

        float o = bb2;
        #pragma unroll
        for (int k = 0; k < 32; k++) {
            float hk = __shfl_sync(0xffffffffu, h, k);
            o = fmaf(hk, w2c[k], o);
        }
        g_lut[(size_t)idx * 32 + lane] = fmaxf(o, 0.0f);
    }
}

#define WARPS_PER_BLOCK 8
#define ROWS_PER_WARP 2
#define HASH_SLOTS 512      // 16 KB/block

// Count uniques for one row's 4 tokens. row_tag is 0 or 128 (row bit).
// Hashes are rematerialized at each use to minimize live registers.
__device__ __forceinline__ int count_uniques(int* tab, const int4& iv,
                                             const int4& mv, int lane,
                                             int row_tag) {
    int vals[4] = {iv.x, iv.y, iv.z, iv.w};
    bool pend[4] = {mv.x != 0, mv.y != 0, mv.z != 0, mv.w != 0};

    int base_pos = row_tag + lane * 4;
    int pack[4];
    #pragma unroll
    for (int t = 0; t < 4; t++)
        pack[t] = vals[t] * 256 + (base_pos + t);   // (v<<8)|(row<<7)|pos

    int cnt = 0;

    // round 0: direct-mapped (hash = v & 511, rematerialized: 1 AND)
    #pragma unroll
    for (int t = 0; t < 4; t++)
        if (pend[t]) tab[(unsigned)vals[t] & (HASH_SLOTS - 1)] = pack[t];
    __syncwarp();                      // writes before reads (required)
    #pragma unroll
    for (int t = 0; t < 4; t++) {
        if (pend[t]) {
            int x = tab[(unsigned)vals[t] & (HASH_SLOTS - 1)] ^ pack[t];
            if ((unsigned)x < 128u) { pend[t] = false; cnt += (x == 0); }
        }
    }
    // no syncwarp: benign-misread analysis (header)

    // round 1: multiplicative hash, survivors only (remat: IMAD+SHR)
    #pragma unroll
    for (int t = 0; t < 4; t++)
        if (pend[t]) tab[((unsigned)vals[t] * 2654435761u) >> 23] = pack[t];
    __syncwarp();                      // writes before reads (required)
    #pragma unroll
    for (int t = 0; t < 4; t++) {
        if (pend[t]) {
            int x = tab[((unsigned)vals[t] * 2654435761u) >> 23] ^ pack[t];
            if ((unsigned)x < 128u) { pend[t] = false; cnt += (x == 0); }
        }
    }

    // tail: smem-free cohort broadcast (exact; ~0 iterations typical).
    // The unconditional ballot also row-isolates successive calls.
    while (true) {
        bool any = pend[0] | pend[1] | pend[2] | pend[3];
        unsigned m = __ballot_sync(0xffffffffu, any);
        if (!m) break;
        int leader = __ffs(m) - 1;
        int myv = pend[0] ? vals[0] : pend[1] ? vals[1]
                : pend[2] ? vals[2] : vals[3];
        int lv = __shfl_sync(0xffffffffu, myv, leader);
        cnt += (lane == leader);
        #pragma unroll
        for (int t = 0; t < 4; t++)
            pend[t] &= (vals[t] != lv);
    }
    return cnt;
}

__global__ __launch_bounds__(WARPS_PER_BLOCK * 32, 8)
void feat_kernel(const int* __restrict__ ids, const int* __restrict__ mask,
                 float* __restrict__ out, int B) {
    __shared__ int table[WARPS_PER_BLOCK][HASH_SLOTS];

    int w    = threadIdx.x >> 5;
    int lane = threadIdx.x & 31;
    int row0 = (blockIdx.x * WARPS_PER_BLOCK + w) * ROWS_PER_WARP;
    if (row0 >= B) return;
    int row1 = row0 + 1;    // B is a multiple of 16 -> always valid here

    int* tab = table[w];

    // Front-batch all 4 input loads (MLP 4, streaming to protect L2 LUT).
    const int4* id0 = (const int4*)(ids  + (size_t)row0 * MAX_LEN);
    const int4* mk0 = (const int4*)(mask + (size_t)row0 * MAX_LEN);
    int4 iv0 = __ldcs(id0 + lane);
    int4 mv0 = __ldcs(mk0 + lane);
    int4 iv1 = __ldcs(id0 + (MAX_LEN / 4) + lane);   // row1 = row0+1, contiguous
    int4 mv1 = __ldcs(mk0 + (MAX_LEN / 4) + lane);

    int seq0 = mv0.x + mv0.y + mv0.z + mv0.w;
    int seq1 = mv1.x + mv1.y + mv1.z + mv1.w;

    int cnt0 = count_uniques(tab, iv0, mv0, lane, 0);
    int cnt1 = count_uniques(tab, iv1, mv1, lane, 128);

    // LUT index is linear in per-lane partials: one REDUX per row.
    int idx0 = __reduce_add_sync(0xffffffffu, seq0 * LUT_DIM + cnt0);
    int idx1 = __reduce_add_sync(0xffffffffu, seq1 * LUT_DIM + cnt1);

    float v0 = g_lut[(size_t)idx0 * 32 + lane];
    float v1 = g_lut[(size_t)idx1 * 32 + lane];
    __stcs(&out[(size_t)row0 * 32 + lane], v0);
    __stcs(&out[(size_t)row1 * 32 + lane], v1);
}

extern "C" void kernel_launch(void* const* d_in, const int* in_sizes, int n_in,
                              void* d_out, int out_size) {
    const int*   ids  = (const int*)d_in[0];
    const int*   mask = (const int*)d_in[1];
    const float* W1   = (const float*)d_in[2];
    const float* b1   = (const float*)d_in[3];
    const float* W2   = (const float*)d_in[4];
    const float* b2   = (const float*)d_in[5];
    float* out = (float*)d_out;

    int B = in_sizes[0] / MAX_LEN;

    int lut_pairs  = LUT_DIM * LUT_DIM;
    int pairs_per_block = 8 * LUT_PAIRS_PER_WARP;
    int lut_blocks = (lut_pairs + pairs_per_block - 1) / pairs_per_block;
    build_lut_kernel<<<lut_blocks, 256>>>(W1, b1, W2, b2);

    int rows_per_block = WARPS_PER_BLOCK * ROWS_PER_WARP;
    int blocks = (B + rows_per_block - 1) / rows_per_block;
    feat_kernel<<<blocks, WARPS_PER_BLOCK * 32>>>(ids, mask, out, B);
}

// round 16
// speedup vs baseline: 1.5598x; 1.0090x over previous
#include <cuda_runtime.h>
#include <cuda_bf16.h>
#include <cstdint>

// ---------------------------------------------------------------------------
// SymbolicFeatureExtractor: per-row (seq_len, unique_count) -> 3 feats -> MLP.
// MLP output depends only on (seq_len, uniq) in [0,128]^2 -> 129x129x32 LUT
// (2.1 MB, L2-resident; inputs/outputs use streaming hints to protect it).
//
// R16 = R15 champion feat kernel (two rows per warp, 512-slot per-warp
// table, no clears, 32 regs -> 8 blocks/SM) with:
//   * one packed REDUX for both rows (p0 + p1<<16; each row's warp sum
//     <= 16640 < 2^16, so no carry between halves), and
//   * a ~4x faster build_lut (2 pairs/warp -> 1041 blocks; layer-2 dot
//     product split into 4 independent FMA accumulators to break the
//     serial dependence chain).
//
// Unique counting (proven R8/R11/R15): pack = v*256 + row*128 + pos;
// x = slot^pack; x<128 <=> value AND row match (cohort resolved; the x==0
// member is the unique winner, counts 1). Hashes rematerialized at the read
// site to hold 32 registers. One syncwarp after each round's writes; none
// between reads and next writes (benign-misread: a misdirected resolve
// never has x==0; cohort still counted exactly once by the round-1 winner
// or the exact tail loop). Row isolation via the tail loop's unconditional
// ballot + row bit. No clears ever: every read is preceded by that token's
// own same-round write to the same slot.
// ---------------------------------------------------------------------------

#define MAX_LEN 128
#define LUT_DIM 129

__device__ float g_lut[LUT_DIM * LUT_DIM * 32];

#define LUT_PAIRS_PER_WARP 2

__global__ __launch_bounds__(256)
void build_lut_kernel(const float* __restrict__ W1, const float* __restrict__ b1,
                      const float* __restrict__ W2, const float* __restrict__ b2) {
    int warp_in_block = threadIdx.x >> 5;
    int lane = threadIdx.x & 31;
    int base = (blockIdx.x * (blockDim.x >> 5) + warp_in_block) * LUT_PAIRS_PER_WARP;
    if (base >= LUT_DIM * LUT_DIM) return;

    float w10 = W1[0 * 32 + lane];
    float w11 = W1[1 * 32 + lane];
    float w12 = W1[2 * 32 + lane];
    float bb1 = b1[lane];
    float bb2 = b2[lane];
    float w2c[32];
    #pragma unroll
    for (int k = 0; k < 32; k++) w2c[k] = W2[k * 32 + lane];

    #pragma unroll
    for (int p = 0; p < LUT_PAIRS_PER_WARP; p++) {
        int idx = base + p;
        if (idx >= LUT_DIM * LUT_DIM) break;
        int s = idx / LUT_DIM;
        int u = idx % LUT_DIM;

        float f0 = (float)s * (1.0f / MAX_LEN);
        float f1 = (float)u * (1.0f / MAX_LEN);
        float f2 = (s > 0) ? ((float)u / (float)s) : 0.0f;

        float h = bb1;
        h = fmaf(f0, w10, h);
        h = fmaf(f1, w11, h);
        h = fmaf(f2, w12, h);
        h = fmaxf(h, 0.0f);

        // Layer 2: 4 independent accumulators break the serial FMA chain
        // (lat 4 each -> ~40-cycle chain instead of ~128).
        float o0 = bb2, o1 = 0.0f, o2 = 0.0f, o3 = 0.0f;
        #pragma unroll
        for (int k = 0; k < 32; k += 4) {
            float h0 = __shfl_sync(0xffffffffu, h, k + 0);
            float h1 = __shfl_sync(0xffffffffu, h, k + 1);
            float h2 = __shfl_sync(0xffffffffu, h, k + 2);
            float h3 = __shfl_sync(0xffffffffu, h, k + 3);
            o0 = fmaf(h0, w2c[k + 0], o0);
            o1 = fmaf(h1, w2c[k + 1], o1);
            o2 = fmaf(h2, w2c[k + 2], o2);
            o3 = fmaf(h3, w2c[k + 3], o3);
        }
        float o = (o0 + o1) + (o2 + o3);
        g_lut[(size_t)idx * 32 + lane] = fmaxf(o, 0.0f);
    }
}

#define WARPS_PER_BLOCK 8
#define ROWS_PER_WARP 2
#define HASH_SLOTS 512      // 16 KB/block -> 8 blocks/SM at 32 regs

// Count uniques for one row's 4 tokens. row_tag is 0 or 128 (row bit).
// Hashes are rematerialized at each use to minimize live registers.
__device__ __forceinline__ int count_uniques(int* tab, const int4& iv,
                                             const int4& mv, int lane,
                                             int row_tag) {
    int vals[4] = {iv.x, iv.y, iv.z, iv.w};
    bool pend[4] = {mv.x != 0, mv.y != 0, mv.z != 0, mv.w != 0};

    int base_pos = row_tag + lane * 4;
    int pack[4];
    #pragma unroll
    for (int t = 0; t < 4; t++)
        pack[t] = vals[t] * 256 + (base_pos + t);   // (v<<8)|(row<<7)|pos

    int cnt = 0;

    // round 0: direct-mapped (hash = v & 511, rematerialized: 1 AND)
    #pragma unroll
    for (int t = 0; t < 4; t++)
        if (pend[t]) tab[(unsigned)vals[t] & (HASH_SLOTS - 1)] = pack[t];
    __syncwarp();                      // writes before reads (required)
    #pragma unroll
    for (int t = 0; t < 4; t++) {
        if (pend[t]) {
            int x = tab[(unsigned)vals[t] & (HASH_SLOTS - 1)] ^ pack[t];
            if ((unsigned)x < 128u) { pend[t] = false; cnt += (x == 0); }
        }
    }
    // no syncwarp: benign-misread analysis (header)

    // round 1: multiplicative hash, survivors only (remat: IMAD+SHR)
    #pragma unroll
    for (int t = 0; t < 4; t++)
        if (pend[t]) tab[((unsigned)vals[t] * 2654435761u) >> 23] = pack[t];
    __syncwarp();                      // writes before reads (required)
    #pragma unroll
    for (int t = 0; t < 4; t++) {
        if (pend[t]) {
            int x = tab[((unsigned)vals[t] * 2654435761u) >> 23] ^ pack[t];
            if ((unsigned)x < 128u) { pend[t] = false; cnt += (x == 0); }
        }
    }

    // tail: smem-free cohort broadcast (exact; ~0 iterations typical).
    // The unconditional ballot also row-isolates successive calls.
    while (true) {
        bool any = pend[0] | pend[1] | pend[2] | pend[3];
        unsigned m = __ballot_sync(0xffffffffu, any);
        if (!m) break;
        int leader = __ffs(m) - 1;
        int myv = pend[0] ? vals[0] : pend[1] ? vals[1]
                : pend[2] ? vals[2] : vals[3];
        int lv = __shfl_sync(0xffffffffu, myv, leader);
        cnt += (lane == leader);
        #pragma unroll
        for (int t = 0; t < 4; t++)
            pend[t] &= (vals[t] != lv);
    }
    return cnt;
}

__global__ __launch_bounds__(WARPS_PER_BLOCK * 32, 8)
void feat_kernel(const int* __restrict__ ids, const int* __restrict__ mask,
                 float* __restrict__ out, int B) {
    __shared__ int table[WARPS_PER_BLOCK][HASH_SLOTS];

    int w    = threadIdx.x >> 5;
    int lane = threadIdx.x & 31;
    int row0 = (blockIdx.x * WARPS_PER_BLOCK + w) * ROWS_PER_WARP;
    if (row0 >= B) return;
    int row1 = row0 + 1;    // B is a multiple of 16 -> always valid here

    int* tab = table[w];

    // Front-batch all 4 input loads (MLP 4, streaming to protect L2 LUT).
    const int4* id0 = (const int4*)(ids  + (size_t)row0 * MAX_LEN);
    const int4* mk0 = (const int4*)(mask + (size_t)row0 * MAX_LEN);
    int4 iv0 = __ldcs(id0 + lane);
    int4 mv0 = __ldcs(mk0 + lane);
    int4 iv1 = __ldcs(id0 + (MAX_LEN / 4) + lane);   // row1 = row0+1, contiguous
    int4 mv1 = __ldcs(mk0 + (MAX_LEN / 4) + lane);

    int seq0 = mv0.x + mv0.y + mv0.z + mv0.w;
    int seq1 = mv1.x + mv1.y + mv1.z + mv1.w;

    int cnt0 = count_uniques(tab, iv0, mv0, lane, 0);
    int cnt1 = count_uniques(tab, iv1, mv1, lane, 128);

    // One packed REDUX for both rows: per-row warp sums <= 16640 < 2^16,
    // so the low half can never carry into the high half.
    int packed = (seq0 * LUT_DIM + cnt0) + ((seq1 * LUT_DIM + cnt1) << 16);
    int summed = __reduce_add_sync(0xffffffffu, packed);
    int idx0 = summed & 0xFFFF;
    int idx1 = summed >> 16;

    float v0 = g_lut[(size_t)idx0 * 32 + lane];
    float v1 = g_lut[(size_t)idx1 * 32 + lane];
    __stcs(&out[(size_t)row0 * 32 + lane], v0);
    __stcs(&out[(size_t)row1 * 32 + lane], v1);
}

extern "C" void kernel_launch(void* const* d_in, const int* in_sizes, int n_in,
                              void* d_out, int out_size) {
    const int*   ids  = (const int*)d_in[0];
    const int*   mask = (const int*)d_in[1];
    const float* W1   = (const float*)d_in[2];
    const float* b1   = (const float*)d_in[3];
    const float* W2   = (const float*)d_in[4];
    const float* b2   = (const float*)d_in[5];
    float* out = (float*)d_out;

    int B = in_sizes[0] / MAX_LEN;

    int lut_pairs  = LUT_DIM * LUT_DIM;
    int pairs_per_block = 8 * LUT_PAIRS_PER_WARP;   // 16
    int lut_blocks = (lut_pairs + pairs_per_block - 1) / pairs_per_block;
    build_lut_kernel<<<lut_blocks, 256>>>(W1, b1, W2, b2);

    int rows_per_block = WARPS_PER_BLOCK * ROWS_PER_WARP;
    int blocks = (B + rows_per_block - 1) / rows_per_block;
    feat_kernel<<<blocks, WARPS_PER_BLOCK * 32>>>(ids, mask, out, B);
}